// round 6
// baseline (speedup 1.0000x reference)
#include <cuda_runtime.h>
#include <cuda_bf16.h>
#include <cuda_fp16.h>
#include <cstdint>

#define BATCH 256
#define SEQ   256
#define EMBD  512
#define HEAD  64
#define ROWS  (BATCH * SEQ)      // 65536

__device__ float g_q[ROWS * HEAD];
__device__ float g_k[ROWS * HEAD];
__device__ float g_v[ROWS * HEAD];

// ===========================================================================
// Helpers
// ===========================================================================
__device__ __forceinline__ float tf32_rna(float x) {
    float y;
    asm("cvt.rna.tf32.f32 %0, %1;" : "=f"(y) : "f"(x));
    return y;
}

__device__ __forceinline__ void mma_tf32(float& c0, float& c1, float& c2, float& c3,
                                         uint32_t a0, uint32_t a1, uint32_t a2, uint32_t a3,
                                         uint32_t b0, uint32_t b1) {
    asm volatile(
        "mma.sync.aligned.m16n8k8.row.col.f32.tf32.tf32.f32 "
        "{%0,%1,%2,%3}, {%4,%5,%6,%7}, {%8,%9}, {%0,%1,%2,%3};"
        : "+f"(c0), "+f"(c1), "+f"(c2), "+f"(c3)
        : "r"(a0), "r"(a1), "r"(a2), "r"(a3), "r"(b0), "r"(b1));
}

__device__ __forceinline__ void mma_f16(float& c0, float& c1, float& c2, float& c3,
                                        uint32_t a0, uint32_t a1, uint32_t a2, uint32_t a3,
                                        uint32_t b0, uint32_t b1) {
    asm volatile(
        "mma.sync.aligned.m16n8k16.row.col.f32.f16.f16.f32 "
        "{%0,%1,%2,%3}, {%4,%5,%6,%7}, {%8,%9}, {%0,%1,%2,%3};"
        : "+f"(c0), "+f"(c1), "+f"(c2), "+f"(c3)
        : "r"(a0), "r"(a1), "r"(a2), "r"(a3), "r"(b0), "r"(b1));
}

__device__ __forceinline__ uint32_t pack_h2(float lo, float hi) {
    __half2 h = __floats2half2_rn(lo, hi);
    return *(uint32_t*)&h;
}

// ===========================================================================
// Stage 1: fused QKV projection, mma.sync tf32.
// CTA: 512 threads / 16 warps = 4 row-groups x 4 col-groups.
//   warp tile: 32 rows (mt=2 x m16) x 48 cols (6 x n8).
// Tile M=128, N=192 (K|Q|V), K-chunk=32. Double-buffered fragment-packed
// smem; ONE syncthreads per chunk.
// ===========================================================================
#define KCHUNK 32
#define NCHNK  (EMBD / KCHUNK)   // 16
#define STAGE_SZ 40960           // 16KB A-frags + 24KB B-frags
#define SG_A(buf)  ((buf) * STAGE_SZ)
#define SG_B(buf)  ((buf) * STAGE_SZ + 16384)
#define SG_BIAS    (2 * STAGE_SZ)
#define GEMM_SMEM  (SG_BIAS + 768)

__global__ __launch_bounds__(512, 1) void qkv_gemm_mma(
    const float* __restrict__ x,
    const float* __restrict__ Wk, const float* __restrict__ Wq, const float* __restrict__ Wv,
    const float* __restrict__ bk, const float* __restrict__ bq, const float* __restrict__ bv)
{
    extern __shared__ char sm[];

    const int tid  = threadIdx.x;
    const int wid  = tid >> 5;
    const int lane = tid & 31;
    const int rg   = wid >> 2;        // row-group 0..3
    const int cg   = wid & 3;         // col-group 0..3
    const int g    = lane >> 2;
    const int t    = lane & 3;
    const int row0 = blockIdx.x * 128;

    if (tid < 192) {
        const float* bsr = (tid < 64) ? bk : (tid < 128) ? bq : bv;
        ((float*)(sm + SG_BIAS))[tid] = bsr[tid & 63];
    }

    const float* asrc[2];
#pragma unroll
    for (int i = 0; i < 2; i++) {
        int f4 = tid + i * 512;       // 0..1023
        int r = f4 >> 3, c4 = f4 & 7;
        asrc[i] = x + (size_t)(row0 + r) * EMBD + c4 * 4;
    }
    const float* bsrc[3];
#pragma unroll
    for (int i = 0; i < 3; i++) {
        int f4 = tid + i * 512;       // 0..1535
        int k = f4 / 48, c4 = f4 % 48;
        int m = c4 >> 4, w4 = c4 & 15;
        const float* W = (m == 0) ? Wk : (m == 1) ? Wq : Wv;
        bsrc[i] = W + (size_t)k * HEAD + w4 * 4;
    }

    float acc[2][6][4];
#pragma unroll
    for (int mt = 0; mt < 2; mt++)
#pragma unroll
        for (int nt = 0; nt < 6; nt++)
#pragma unroll
            for (int j = 0; j < 4; j++) acc[mt][nt][j] = 0.f;

    float4 pa[2], pb[3];

#define LDCHUNK(k0)                                                      \
    do {                                                                 \
        _Pragma("unroll")                                                \
        for (int i = 0; i < 2; i++) pa[i] = *(const float4*)(asrc[i] + (k0)); \
        _Pragma("unroll")                                                \
        for (int i = 0; i < 3; i++) pb[i] = *(const float4*)(bsrc[i] + (size_t)(k0) * HEAD); \
    } while (0)

#define STCHUNK(buf)                                                     \
    do {                                                                 \
        _Pragma("unroll")                                                \
        for (int i = 0; i < 2; i++) {                                    \
            int f4 = tid + i * 512;                                      \
            int r = f4 >> 3, c4 = f4 & 7;                                \
            int ks = c4 >> 1, rl = r & 15;                               \
            int regb = ((c4 & 1) << 1) | (rl >> 3);                      \
            int lbase = (rl & 7) << 2;                                   \
            int region = SG_A(buf) + (((r >> 4) * 4) + ks) * 512;        \
            float e[4] = {tf32_rna(pa[i].x), tf32_rna(pa[i].y),          \
                          tf32_rna(pa[i].z), tf32_rna(pa[i].w)};         \
            _Pragma("unroll")                                            \
            for (int j = 0; j < 4; j++) {                                \
                int l = lbase | j;                                       \
                *(float*)(sm + region + (((l * 16) ^ (ks << 5)) + regb * 4)) = e[j]; \
            }                                                            \
        }                                                                \
        _Pragma("unroll")                                                \
        for (int i = 0; i < 3; i++) {                                    \
            int f4 = tid + i * 512;                                      \
            int k = f4 / 48, c4 = f4 % 48;                               \
            int ks = k >> 3, kin = k & 7;                                \
            int regb = kin >> 2, kin3 = kin & 3;                         \
            int nt = c4 >> 1, nb = (c4 & 1) * 4;                         \
            int bsw = ((nt & 3) << 5) | ((nt >> 2) << 3);                \
            int region = SG_B(buf) + (ks * 24 + nt) * 256;               \
            float e[4] = {tf32_rna(pb[i].x), tf32_rna(pb[i].y),          \
                          tf32_rna(pb[i].z), tf32_rna(pb[i].w)};         \
            _Pragma("unroll")                                            \
            for (int j = 0; j < 4; j++) {                                \
                int l = ((nb + j) << 2) | kin3;                          \
                *(float*)(sm + region + (((l * 8) ^ bsw) + regb * 4)) = e[j]; \
            }                                                            \
        }                                                                \
    } while (0)

    LDCHUNK(0);
    STCHUNK(0);
    __syncthreads();

    for (int c = 0; c < NCHNK; ++c) {
        const int buf = c & 1;
        if (c + 1 < NCHNK) LDCHUNK((c + 1) * KCHUNK);

#pragma unroll
        for (int ks = 0; ks < 4; ks++) {
            uint4 af[2];
#pragma unroll
            for (int mt = 0; mt < 2; mt++)
                af[mt] = *(const uint4*)(sm + SG_A(buf) + ((rg * 2 + mt) * 4 + ks) * 512 +
                                         ((lane * 16) ^ (ks << 5)));
#pragma unroll
            for (int nt = 0; nt < 6; nt++) {
                int ntg = cg * 6 + nt;
                int bsw = ((ntg & 3) << 5) | ((ntg >> 2) << 3);
                uint2 bf = *(const uint2*)(sm + SG_B(buf) + (ks * 24 + ntg) * 256 +
                                           ((lane * 8) ^ bsw));
#pragma unroll
                for (int mt = 0; mt < 2; mt++)
                    mma_tf32(acc[mt][nt][0], acc[mt][nt][1], acc[mt][nt][2], acc[mt][nt][3],
                             af[mt].x, af[mt].y, af[mt].z, af[mt].w, bf.x, bf.y);
            }
        }

        if (c + 1 < NCHNK) {
            STCHUNK(buf ^ 1);
            __syncthreads();
        }
    }

    const float* sbias = (const float*)(sm + SG_BIAS);
#pragma unroll
    for (int mt = 0; mt < 2; mt++) {
        int r0 = row0 + rg * 32 + mt * 16 + g;
#pragma unroll
        for (int nt = 0; nt < 6; nt++) {
            int ntg = cg * 6 + nt;
            float* out = (ntg < 8) ? g_k : (ntg < 16) ? g_q : g_v;
            int col  = ntg * 8 + t * 2;
            int wcol = col & 63;
            float b0 = sbias[col], b1 = sbias[col + 1];
            *(float2*)&out[(size_t)r0 * HEAD + wcol] =
                make_float2(acc[mt][nt][0] + b0, acc[mt][nt][1] + b1);
            *(float2*)&out[(size_t)(r0 + 8) * HEAD + wcol] =
                make_float2(acc[mt][nt][2] + b0, acc[mt][nt][3] + b1);
        }
    }
#undef LDCHUNK
#undef STCHUNK
}

// ===========================================================================
// Stage 2: flash attention. QK^T in tf32 mma; PV in fp16 m16n8k16 mma:
// S C-frag packs DIRECTLY into fp16 A-frag (half2 of (c0,c1)/(c2,c3)) -> no
// shuffles, half the PV instructions. V stored fp16 (32KB) + K tf32 (64KB)
// = 96KB smem -> 2 CTAs/SM, single wave over 256 CTAs.
// Each warp processes query tiles {wid, 15-wid} -> balanced 5 key-blocks.
// ===========================================================================
#define ATT_SMEM (SEQ * HEAD * 4 + SEQ * HEAD * 2)   // 96KB

__global__ __launch_bounds__(256, 2) void attn_mma(float* __restrict__ out)
{
    extern __shared__ char asm_[];
    float* sKp  = (float*)asm_;                        // 64KB tf32 K frags
    __half* sVp = (__half*)(asm_ + SEQ * HEAD * 4);    // 32KB fp16 V frags

    const int b    = blockIdx.x;
    const int tid  = threadIdx.x;
    const int wid  = tid >> 5;
    const int lane = tid & 31;
    const int g    = lane >> 2;
    const int t    = lane & 3;

    // ---- cooperative fragment-pack: K (tf32) + V (fp16) ----
    const float* kg = g_k + (size_t)b * SEQ * HEAD;
    const float* vg = g_v + (size_t)b * SEQ * HEAD;
    for (int i = tid; i < SEQ * HEAD / 4; i += 256) {
        int s = i >> 4, h4 = i & 15;
        float4 kv = *(const float4*)&kg[s * HEAD + h4 * 4];
        float* rb = sKp + ((s >> 3) * 8 + (h4 >> 1)) * 64 + ((s & 7) << 3) + (h4 & 1);
        rb[0] = tf32_rna(kv.x); rb[2] = tf32_rna(kv.y);
        rb[4] = tf32_rna(kv.z); rb[6] = tf32_rna(kv.w);

        // V fp16 B-frags for m16n8k16: region (kb16, nf) = 32 lanes x 2 regs.
        //   b0 = {V[2t'][n], V[2t'+1][n]}, b1 = {V[2t'+8][n], V[2t'+9][n]}
        float4 vv = *(const float4*)&vg[s * HEAD + h4 * 4];
        int kb16 = s >> 4, k = s & 15;
        int reg = k >> 3, hlf = k & 1, tq = (k & 7) >> 1;
        float ve[4] = {vv.x, vv.y, vv.z, vv.w};
#pragma unroll
        for (int j = 0; j < 4; j++) {
            int h = h4 * 4 + j;
            int nf = h >> 3, n = h & 7;
            sVp[((kb16 * 8 + nf) * 128) + ((n << 2) | tq) * 4 + reg * 2 + hlf] =
                __float2half_rn(ve[j]);
        }
    }
    __syncthreads();

#pragma unroll
    for (int pass = 0; pass < 2; pass++) {
        const int qt = pass ? (15 - wid) : wid;
        const int q0 = qt * 16;
        const int kb_hi = q0 >> 6;

        const float* qg = g_q + ((size_t)b * SEQ + q0) * HEAD;
        uint32_t qa[8][4];
#pragma unroll
        for (int ks = 0; ks < 8; ks++) {
            qa[ks][0] = __float_as_uint(tf32_rna(qg[(size_t)g * HEAD + ks * 8 + t]));
            qa[ks][1] = __float_as_uint(tf32_rna(qg[(size_t)(g + 8) * HEAD + ks * 8 + t]));
            qa[ks][2] = __float_as_uint(tf32_rna(qg[(size_t)g * HEAD + ks * 8 + t + 4]));
            qa[ks][3] = __float_as_uint(tf32_rna(qg[(size_t)(g + 8) * HEAD + ks * 8 + t + 4]));
        }

        float m0 = -1e30f, m1 = -1e30f, l0 = 0.f, l1 = 0.f;
        float o[8][4];
#pragma unroll
        for (int nf = 0; nf < 8; nf++)
#pragma unroll
            for (int j = 0; j < 4; j++) o[nf][j] = 0.f;

        for (int kb = 0; kb <= kb_hi; kb++) {
            // ---- S = Q K^T (tf32) ----
            float sacc[8][4];
#pragma unroll
            for (int nf = 0; nf < 8; nf++)
#pragma unroll
                for (int j = 0; j < 4; j++) sacc[nf][j] = 0.f;

#pragma unroll
            for (int ks = 0; ks < 8; ks++) {
                uint2 bf[8];
#pragma unroll
                for (int nf = 0; nf < 8; nf++)
                    bf[nf] = *(const uint2*)(sKp + ((kb * 8 + nf) * 8 + ks) * 64 + lane * 2);
#pragma unroll
                for (int nf = 0; nf < 8; nf++)
                    mma_tf32(sacc[nf][0], sacc[nf][1], sacc[nf][2], sacc[nf][3],
                             qa[ks][0], qa[ks][1], qa[ks][2], qa[ks][3],
                             bf[nf].x, bf[nf].y);
            }

            // ---- scale + causal mask ----
            const float SC = 0.125f;
            if (kb == kb_hi) {
                const int row0 = q0 + g, row1 = row0 + 8;
#pragma unroll
                for (int nf = 0; nf < 8; nf++) {
                    int col = kb * 64 + nf * 8 + 2 * t;
                    sacc[nf][0] = (col     <= row0) ? sacc[nf][0] * SC : -1e30f;
                    sacc[nf][1] = (col + 1 <= row0) ? sacc[nf][1] * SC : -1e30f;
                    sacc[nf][2] = (col     <= row1) ? sacc[nf][2] * SC : -1e30f;
                    sacc[nf][3] = (col + 1 <= row1) ? sacc[nf][3] * SC : -1e30f;
                }
            } else {
#pragma unroll
                for (int nf = 0; nf < 8; nf++)
#pragma unroll
                    for (int j = 0; j < 4; j++) sacc[nf][j] *= SC;
            }

            // ---- online softmax (rows g, g+8) ----
            float mx0 = -1e30f, mx1 = -1e30f;
#pragma unroll
            for (int nf = 0; nf < 8; nf++) {
                mx0 = fmaxf(mx0, fmaxf(sacc[nf][0], sacc[nf][1]));
                mx1 = fmaxf(mx1, fmaxf(sacc[nf][2], sacc[nf][3]));
            }
            mx0 = fmaxf(mx0, __shfl_xor_sync(0xffffffffu, mx0, 1));
            mx0 = fmaxf(mx0, __shfl_xor_sync(0xffffffffu, mx0, 2));
            mx1 = fmaxf(mx1, __shfl_xor_sync(0xffffffffu, mx1, 1));
            mx1 = fmaxf(mx1, __shfl_xor_sync(0xffffffffu, mx1, 2));

            float mn0 = fmaxf(m0, mx0), mn1 = fmaxf(m1, mx1);
            float cr0 = __expf(m0 - mn0), cr1 = __expf(m1 - mn1);
            m0 = mn0; m1 = mn1;

            float s0 = 0.f, s1 = 0.f;
#pragma unroll
            for (int nf = 0; nf < 8; nf++) {
                float p0 = __expf(sacc[nf][0] - m0);
                float p1 = __expf(sacc[nf][1] - m0);
                float p2 = __expf(sacc[nf][2] - m1);
                float p3 = __expf(sacc[nf][3] - m1);
                s0 += p0 + p1; s1 += p2 + p3;
                sacc[nf][0] = p0; sacc[nf][1] = p1;
                sacc[nf][2] = p2; sacc[nf][3] = p3;
            }
            s0 += __shfl_xor_sync(0xffffffffu, s0, 1);
            s0 += __shfl_xor_sync(0xffffffffu, s0, 2);
            s1 += __shfl_xor_sync(0xffffffffu, s1, 1);
            s1 += __shfl_xor_sync(0xffffffffu, s1, 2);
            l0 = l0 * cr0 + s0;
            l1 = l1 * cr1 + s1;
#pragma unroll
            for (int nf = 0; nf < 8; nf++) {
                o[nf][0] *= cr0; o[nf][1] *= cr0;
                o[nf][2] *= cr1; o[nf][3] *= cr1;
            }

            // ---- O += P V (fp16 k16): C-frag -> A-frag by packing, no shfl ----
#pragma unroll
            for (int kk = 0; kk < 4; kk++) {
                uint32_t a0 = pack_h2(sacc[2 * kk][0],     sacc[2 * kk][1]);
                uint32_t a1 = pack_h2(sacc[2 * kk][2],     sacc[2 * kk][3]);
                uint32_t a2 = pack_h2(sacc[2 * kk + 1][0], sacc[2 * kk + 1][1]);
                uint32_t a3 = pack_h2(sacc[2 * kk + 1][2], sacc[2 * kk + 1][3]);

#pragma unroll
                for (int nf = 0; nf < 8; nf++) {
                    uint2 vb = *(const uint2*)(sVp + ((kb * 4 + kk) * 8 + nf) * 128 +
                                               lane * 4);
                    mma_f16(o[nf][0], o[nf][1], o[nf][2], o[nf][3],
                            a0, a1, a2, a3, vb.x, vb.y);
                }
            }
        }

        // ---- epilogue ----
        const float il0 = 1.f / l0, il1 = 1.f / l1;
        float* og = out + ((size_t)b * SEQ + q0) * HEAD;
#pragma unroll
        for (int nf = 0; nf < 8; nf++) {
            int col = nf * 8 + 2 * t;
            *(float2*)&og[(size_t)g * HEAD + col] =
                make_float2(o[nf][0] * il0, o[nf][1] * il0);
            *(float2*)&og[(size_t)(g + 8) * HEAD + col] =
                make_float2(o[nf][2] * il1, o[nf][3] * il1);
        }
    }
}

// ===========================================================================
extern "C" void kernel_launch(void* const* d_in, const int* in_sizes, int n_in,
                              void* d_out, int out_size)
{
    const float* x  = (const float*)d_in[0];
    const float* Wk = (const float*)d_in[1];
    const float* bk = (const float*)d_in[2];
    const float* Wq = (const float*)d_in[3];
    const float* bq = (const float*)d_in[4];
    const float* Wv = (const float*)d_in[5];
    const float* bv = (const float*)d_in[6];
    float* out = (float*)d_out;
    (void)in_sizes; (void)n_in; (void)out_size;

    cudaFuncSetAttribute(qkv_gemm_mma,
                         cudaFuncAttributeMaxDynamicSharedMemorySize, GEMM_SMEM);
    cudaFuncSetAttribute(attn_mma,
                         cudaFuncAttributeMaxDynamicSharedMemorySize, ATT_SMEM);

    qkv_gemm_mma<<<ROWS / 128, 512, GEMM_SMEM>>>(x, Wk, Wq, Wv, bk, bq, bv);
    attn_mma<<<BATCH, 256, ATT_SMEM>>>(out);
}